// round 2
// baseline (speedup 1.0000x reference)
#include <cuda_runtime.h>
#include <cuda_bf16.h>

// FieldAwareFM: out[b] = sum over 780 field pairs (a<b) of
//   dot(x[b, a, b-1, :], x[b, b, a, :]),  x = input reshaped (bs, 40, 39, 16).
// Every (field, col) slot belongs to exactly one pair, so summing
// x[e] * x[partner(e)] over ALL elements and scaling by 0.5 is exact.
//
// partner(f = i*39 + j) = (j+1)*39 + i   if j >= i
//                       = j*39 + (i-1)   if j <  i
//
// R2 change vs R1: 128-thread blocks @ occupancy 14 so that all 2048 blocks
// are resident in ONE wave (152*14 = 2128 >= 2048), eliminating the 2-wave
// quantization that capped DRAM at 69%. Fixed trip-count main loop (48 iters)
// + 96-thread remainder for clean load batching.

#define NUM_FIELDS 40
#define COLS 39              // NUM_FIELDS - 1
#define EMB 16
#define ROW_FLOATS (NUM_FIELDS * COLS * EMB)   // 24960
#define ROW_F4 (ROW_FLOATS / 4)                // 6240
#define THREADS 128
#define MAIN_ITERS (ROW_F4 / THREADS)          // 48
#define REMAINDER (ROW_F4 - MAIN_ITERS * THREADS)  // 96

__global__ __launch_bounds__(THREADS, 14)
void ffm_pair_dot_kernel(const float* __restrict__ in, float* __restrict__ out)
{
    const int b = blockIdx.x;
    const float4* __restrict__ row = reinterpret_cast<const float4*>(in) + (size_t)b * ROW_F4;

    float acc = 0.0f;

    int e4 = threadIdx.x;
    #pragma unroll 4
    for (int it = 0; it < MAIN_ITERS; ++it, e4 += THREADS) {
        const int f  = e4 >> 2;
        const int d4 = e4 & 3;
        const int i  = f / COLS;               // magic-number IMAD
        const int j  = f - i * COLS;
        const int pf = (j >= i) ? ((j + 1) * COLS + i)
                                : (j * COLS + (i - 1));

        const float4 a = row[e4];
        const float4 p = __ldg(&row[pf * 4 + d4]);
        acc = fmaf(a.x, p.x, acc);
        acc = fmaf(a.y, p.y, acc);
        acc = fmaf(a.z, p.z, acc);
        acc = fmaf(a.w, p.w, acc);
    }

    // remainder: 6240 - 48*128 = 96 elements, threads 0..95
    if (threadIdx.x < REMAINDER) {
        const int f  = e4 >> 2;
        const int d4 = e4 & 3;
        const int i  = f / COLS;
        const int j  = f - i * COLS;
        const int pf = (j >= i) ? ((j + 1) * COLS + i)
                                : (j * COLS + (i - 1));

        const float4 a = row[e4];
        const float4 p = __ldg(&row[pf * 4 + d4]);
        acc = fmaf(a.x, p.x, acc);
        acc = fmaf(a.y, p.y, acc);
        acc = fmaf(a.z, p.z, acc);
        acc = fmaf(a.w, p.w, acc);
    }

    // ---- block reduction ----
    #pragma unroll
    for (int o = 16; o > 0; o >>= 1)
        acc += __shfl_down_sync(0xffffffffu, acc, o);

    __shared__ float warp_sums[THREADS / 32];
    if ((threadIdx.x & 31) == 0)
        warp_sums[threadIdx.x >> 5] = acc;
    __syncthreads();

    if (threadIdx.x < (THREADS / 32)) {
        acc = warp_sums[threadIdx.x];
        #pragma unroll
        for (int o = (THREADS / 64); o > 0; o >>= 1)
            acc += __shfl_down_sync(0x0000000fu, acc, o);
        if (threadIdx.x == 0)
            out[b] = 0.5f * acc;
    }
}

extern "C" void kernel_launch(void* const* d_in, const int* in_sizes, int n_in,
                              void* d_out, int out_size)
{
    const float* in = (const float*)d_in[0];
    float* out = (float*)d_out;
    const int bs = in_sizes[0] / ROW_FLOATS;   // 2048
    ffm_pair_dot_kernel<<<bs, THREADS>>>(in, out);
}

// round 3
// speedup vs baseline: 1.3279x; 1.3279x over previous
#include <cuda_runtime.h>
#include <cuda_bf16.h>

// FieldAwareFM: out[b] = sum over 780 field pairs (a<b) of
//   dot(x[b, a, b-1, :], x[b, b, a, :]),  x = input reshaped (bs, 40, 39, 16).
//
// R3: read-each-element-ONCE traversal. Enumerate only the 780 upper-triangle
// slots s -> (i, j) with j >= i; load upper slot f = i*39+j (contiguous
// stream) and its partner (j+1)*39+i (one 64B chunk per slot), multiply,
// accumulate. No cache-dependent re-reads => DRAM traffic == input size
// (~204 MB) independent of wave residency (R2's regression was L2 overflow
// on the involution traversal's partner re-reads).
//
// Slot pair table (fA, fB) built once per block into smem (3.1 KB) using the
// triangular inverse i = floor((79 - sqrt(6241-8s))/2); boundaries are exact
// because 6241-8*cum(i) = (2i-79)^2 is a perfect square; a correction step
// guards fp rounding in between.

#define NUM_FIELDS 40
#define COLS 39
#define EMB 16
#define ROW_FLOATS (NUM_FIELDS * COLS * EMB)      // 24960
#define ROW_F4 (ROW_FLOATS / 4)                   // 6240
#define NPAIRS 780
#define WORK (NPAIRS * 4)                         // 3120 float4-pair items per row
#define THREADS 128
#define MAIN_ITERS (WORK / THREADS)               // 24
#define REMAINDER (WORK - MAIN_ITERS * THREADS)   // 48

__global__ __launch_bounds__(THREADS, 14)
void ffm_pair_dot_kernel(const float* __restrict__ in, float* __restrict__ out)
{
    __shared__ unsigned int pair_tab[NPAIRS];   // fA | (fB << 16)
    __shared__ float warp_sums[THREADS / 32];

    // ---- build pair table (once per block) ----
    for (int s = threadIdx.x; s < NPAIRS; s += THREADS) {
        int i = (int)(39.5f - 0.5f * sqrtf((float)(6241 - 8 * s)));
        int c = 39 * i - ((i * (i - 1)) >> 1);          // cum(i)
        if (c > s)                { --i; c -= (39 - i); }
        else if (c + (39 - i) <= s) { c += (39 - i); ++i; }
        const int j  = i + (s - c);                      // j in [i, 38]
        const int fA = i * COLS + j;
        const int fB = (j + 1) * COLS + i;
        pair_tab[s] = (unsigned int)fA | ((unsigned int)fB << 16);
    }
    __syncthreads();

    const int b = blockIdx.x;
    const float4* __restrict__ row =
        reinterpret_cast<const float4*>(in) + (size_t)b * ROW_F4;

    float acc = 0.0f;

    int w = threadIdx.x;
    #pragma unroll 4
    for (int it = 0; it < MAIN_ITERS; ++it, w += THREADS) {
        const int s  = w >> 2;
        const int d4 = w & 3;
        const unsigned int pk = pair_tab[s];
        const int fA = (int)(pk & 0xffffu);
        const int fB = (int)(pk >> 16);

        const float4 a = row[fA * 4 + d4];
        const float4 p = row[fB * 4 + d4];
        acc = fmaf(a.x, p.x, acc);
        acc = fmaf(a.y, p.y, acc);
        acc = fmaf(a.z, p.z, acc);
        acc = fmaf(a.w, p.w, acc);
    }

    // remainder: 3120 - 24*128 = 48 items, threads 0..47
    if (threadIdx.x < REMAINDER) {
        const int s  = w >> 2;
        const int d4 = w & 3;
        const unsigned int pk = pair_tab[s];
        const int fA = (int)(pk & 0xffffu);
        const int fB = (int)(pk >> 16);

        const float4 a = row[fA * 4 + d4];
        const float4 p = row[fB * 4 + d4];
        acc = fmaf(a.x, p.x, acc);
        acc = fmaf(a.y, p.y, acc);
        acc = fmaf(a.z, p.z, acc);
        acc = fmaf(a.w, p.w, acc);
    }

    // ---- block reduction ----
    #pragma unroll
    for (int o = 16; o > 0; o >>= 1)
        acc += __shfl_down_sync(0xffffffffu, acc, o);

    if ((threadIdx.x & 31) == 0)
        warp_sums[threadIdx.x >> 5] = acc;
    __syncthreads();

    if (threadIdx.x < (THREADS / 32)) {
        acc = warp_sums[threadIdx.x];
        #pragma unroll
        for (int o = (THREADS / 64); o > 0; o >>= 1)
            acc += __shfl_down_sync(0x0000000fu, acc, o);
        if (threadIdx.x == 0)
            out[b] = acc;                 // each pair counted once: no 0.5
    }
}

extern "C" void kernel_launch(void* const* d_in, const int* in_sizes, int n_in,
                              void* d_out, int out_size)
{
    const float* in = (const float*)d_in[0];
    float* out = (float*)d_out;
    const int bs = in_sizes[0] / ROW_FLOATS;   // 2048
    ffm_pair_dot_kernel<<<bs, THREADS>>>(in, out);
}

// round 4
// speedup vs baseline: 1.3290x; 1.0009x over previous
#include <cuda_runtime.h>
#include <cuda_bf16.h>

// FieldAwareFM: out[b] = sum over 780 field pairs (a<b) of
//   dot(x[b, a, b-1, :], x[b, b, a, :]),  x = input reshaped (bs, 40, 39, 16).
//
// Read-once traversal (R3): enumerate the 780 upper-triangle slots; load the
// upper slot and its lower partner, multiply, accumulate. DRAM traffic ==
// input size, cache-independent.
//
// R4: latency-exposure fix. Each block processes TWO rows (b, b+1024)
// concurrently -> 4 independent LDG.128 per thread-iter, 2 acc chains;
// occupancy cap relaxed to 8 (grid 1024 still fits one wave: 152*8=1216)
// so ptxas has a 64-reg budget to front-batch loads (R3's occ-14/32-reg cap
// forced serial load->fma, MLP_eff~2, DRAM stuck at 70%).

#define NUM_FIELDS 40
#define COLS 39
#define EMB 16
#define ROW_FLOATS (NUM_FIELDS * COLS * EMB)      // 24960
#define ROW_F4 (ROW_FLOATS / 4)                   // 6240
#define NPAIRS 780
#define WORK (NPAIRS * 4)                         // 3120 float4-pair items per row
#define THREADS 128
#define MAIN_ITERS (WORK / THREADS)               // 24
#define REMAINDER (WORK - MAIN_ITERS * THREADS)   // 48

__global__ __launch_bounds__(THREADS, 8)
void ffm_pair_dot_kernel(const float* __restrict__ in, float* __restrict__ out,
                         int half)
{
    __shared__ unsigned int pair_tab[NPAIRS];     // (fA*4) | (fB*4 << 16)
    __shared__ float warp_sums[2][THREADS / 32];

    // ---- build pair table (once per block; amortized over 2 rows) ----
    for (int s = threadIdx.x; s < NPAIRS; s += THREADS) {
        int i = (int)(39.5f - 0.5f * sqrtf((float)(6241 - 8 * s)));
        int c = 39 * i - ((i * (i - 1)) >> 1);            // cum(i)
        if (c > s)                  { --i; c -= (39 - i); }
        else if (c + (39 - i) <= s) { c += (39 - i); ++i; }
        const int j  = i + (s - c);                       // j in [i, 38]
        const int fA = i * COLS + j;
        const int fB = (j + 1) * COLS + i;
        pair_tab[s] = (unsigned int)(fA * 4) | ((unsigned int)(fB * 4) << 16);
    }
    __syncthreads();

    const float4* __restrict__ row0 =
        reinterpret_cast<const float4*>(in) + (size_t)blockIdx.x * ROW_F4;
    const float4* __restrict__ row1 = row0 + (size_t)half * ROW_F4;

    float acc0 = 0.0f;
    float acc1 = 0.0f;

    int w = threadIdx.x;
    #pragma unroll 2
    for (int it = 0; it < MAIN_ITERS; ++it, w += THREADS) {
        const int s  = w >> 2;
        const int d4 = w & 3;
        const unsigned int pk = pair_tab[s];
        const int eA = (int)(pk & 0xffffu) + d4;
        const int eB = (int)(pk >> 16) + d4;

        const float4 a0 = row0[eA];
        const float4 p0 = row0[eB];
        const float4 a1 = row1[eA];
        const float4 p1 = row1[eB];

        acc0 = fmaf(a0.x, p0.x, acc0);
        acc0 = fmaf(a0.y, p0.y, acc0);
        acc0 = fmaf(a0.z, p0.z, acc0);
        acc0 = fmaf(a0.w, p0.w, acc0);
        acc1 = fmaf(a1.x, p1.x, acc1);
        acc1 = fmaf(a1.y, p1.y, acc1);
        acc1 = fmaf(a1.z, p1.z, acc1);
        acc1 = fmaf(a1.w, p1.w, acc1);
    }

    // remainder: 3120 - 24*128 = 48 items, threads 0..47
    if (threadIdx.x < REMAINDER) {
        const int s  = w >> 2;
        const int d4 = w & 3;
        const unsigned int pk = pair_tab[s];
        const int eA = (int)(pk & 0xffffu) + d4;
        const int eB = (int)(pk >> 16) + d4;

        const float4 a0 = row0[eA];
        const float4 p0 = row0[eB];
        const float4 a1 = row1[eA];
        const float4 p1 = row1[eB];

        acc0 = fmaf(a0.x, p0.x, acc0);
        acc0 = fmaf(a0.y, p0.y, acc0);
        acc0 = fmaf(a0.z, p0.z, acc0);
        acc0 = fmaf(a0.w, p0.w, acc0);
        acc1 = fmaf(a1.x, p1.x, acc1);
        acc1 = fmaf(a1.y, p1.y, acc1);
        acc1 = fmaf(a1.z, p1.z, acc1);
        acc1 = fmaf(a1.w, p1.w, acc1);
    }

    // ---- block reduction (both rows) ----
    #pragma unroll
    for (int o = 16; o > 0; o >>= 1) {
        acc0 += __shfl_down_sync(0xffffffffu, acc0, o);
        acc1 += __shfl_down_sync(0xffffffffu, acc1, o);
    }

    if ((threadIdx.x & 31) == 0) {
        warp_sums[0][threadIdx.x >> 5] = acc0;
        warp_sums[1][threadIdx.x >> 5] = acc1;
    }
    __syncthreads();

    if (threadIdx.x < (THREADS / 32)) {
        acc0 = warp_sums[0][threadIdx.x];
        acc1 = warp_sums[1][threadIdx.x];
        #pragma unroll
        for (int o = (THREADS / 64); o > 0; o >>= 1) {
            acc0 += __shfl_down_sync(0x0000000fu, acc0, o);
            acc1 += __shfl_down_sync(0x0000000fu, acc1, o);
        }
        if (threadIdx.x == 0) {
            out[blockIdx.x]        = acc0;
            out[blockIdx.x + half] = acc1;
        }
    }
}

extern "C" void kernel_launch(void* const* d_in, const int* in_sizes, int n_in,
                              void* d_out, int out_size)
{
    const float* in = (const float*)d_in[0];
    float* out = (float*)d_out;
    const int bs = in_sizes[0] / ROW_FLOATS;   // 2048
    const int half = bs / 2;                   // 1024
    ffm_pair_dot_kernel<<<half, THREADS>>>(in, out, half);
}